// round 3
// baseline (speedup 1.0000x reference)
#include <cuda_runtime.h>
#include <math.h>

#define B_  64
#define N_  2048
#define K_  128
#define J_  10
#define D_  16
#define F_  160   // J_*D_

typedef unsigned long long u64;

// scratch (device globals: no allocation allowed)
__device__ float g_s [B_*K_];        // sum over n of u
__device__ float g_v [B_*J_*K_];     // v[b,j,k] = sum_d W[k,jd]*o[b,j,d]
__device__ float g_p1[B_*J_*K_];     // p after routing iter 1
__device__ float g_p2[B_*J_*K_];     // p after routing iter 2

__device__ __forceinline__ u64 ffma2(u64 a, u64 b, u64 c) {
    u64 d; asm("fma.rn.f32x2 %0, %1, %2, %3;" : "=l"(d) : "l"(a), "l"(b), "l"(c));
    return d;
}
__device__ __forceinline__ u64 pack2(float x, float y) {
    u64 d; asm("mov.b64 %0, {%1, %2};" : "=l"(d) : "f"(x), "f"(y));
    return d;
}
__device__ __forceinline__ float2 unpack2(u64 v) {
    float2 r; asm("mov.b64 {%0, %1}, %2;" : "=f"(r.x), "=f"(r.y) : "l"(v));
    return r;
}
__device__ __forceinline__ u64 f4lo(const float4& v) { return pack2(v.x, v.y); }
__device__ __forceinline__ u64 f4hi(const float4& v) { return pack2(v.z, v.w); }

__global__ void k_init() {
    int i = blockIdx.x * blockDim.x + threadIdx.x;
    if (i < B_*K_) g_s[i] = 0.f;
    if (i < B_*J_*K_) { g_p1[i] = 0.f; g_p2[i] = 0.f; }
}

// s[b,k] = sum_n u[b,n,k]
__global__ void k_sum(const float* __restrict__ u) {
    int b = blockIdx.y;
    int chunk = blockIdx.x;            // 0..7, 256 rows each
    int k4 = threadIdx.x & 31;         // float4 index within row
    int rg = threadIdx.x >> 5;         // 0..7, 32 rows each
    const float4* up = (const float4*)(u + ((size_t)b*N_ + (size_t)chunk*256 + (size_t)rg*32)*K_);
    float4 acc = make_float4(0.f,0.f,0.f,0.f);
#pragma unroll 8
    for (int r = 0; r < 32; r++) {
        float4 t = up[r*32 + k4];
        acc.x += t.x; acc.y += t.y; acc.z += t.z; acc.w += t.w;
    }
    float* sp = g_s + b*K_ + k4*4;
    atomicAdd(sp+0, acc.x); atomicAdd(sp+1, acc.y);
    atomicAdd(sp+2, acc.z); atomicAdd(sp+3, acc.w);
}

// mode 0: o[b,j,d] = 0.1 * sum_k s[b,k]   * W[k, j*16+d]   (uses g_s)
// mode 1: o[b,j,d] =       sum_k p1[b,j,k]* W[k, j*16+d]   (uses g_p1)
// then    v[b,j,k] = sum_d o[b,j,d] * W[k, j*16+d]
__global__ void k_ov(const float* __restrict__ W, int mode) {
    int b = blockIdx.x, t = threadIdx.x;   // 160 threads
    __shared__ float src[J_*K_];
    __shared__ float so[F_];
    if (mode == 0) {
        if (t < K_) src[t] = g_s[b*K_ + t];
    } else {
        for (int i = t; i < J_*K_; i += F_) src[i] = g_p1[b*J_*K_ + i];
    }
    __syncthreads();
    int j = t >> 4;
    float acc = 0.f;
    const float* wcol = W + t;             // W[k*F_ + t]
    if (mode == 0) {
#pragma unroll 8
        for (int k = 0; k < K_; k++) acc += src[k] * wcol[k*F_];
        acc *= 0.1f;
    } else {
        const float* pj = src + j*K_;
#pragma unroll 8
        for (int k = 0; k < K_; k++) acc += pj[k] * wcol[k*F_];
    }
    so[t] = acc;
    __syncthreads();
    for (int e = t; e < J_*K_; e += F_) {
        int jj = e >> 7, k = e & 127;
        const float* wrow = W + k*F_ + jj*D_;
        const float* oj = so + jj*D_;
        float v = 0.f;
#pragma unroll
        for (int d2 = 0; d2 < D_; d2++) v += oj[d2] * wrow[d2];
        g_v[b*J_*K_ + e] = v;
    }
}

// fused: b[j] = u_row . v[j]  -> softmax over j -> p[j,:] += c[j]*u_row
// 8 lanes per row (4 rows/warp-iter): lane (q = lane>>3, s = lane&7) owns
// k = 32i + 4s + e of row q, so every LDG.128 / LDS.128 is a contiguous,
// conflict-free 128B transaction. 3-level butterfly. Coefs shared via
// shfl_xor(8/16/24) with lane-relative (q^r) accum rows. p accumulated in
// registers (k = e*32 + lane), dumped via smem atomics, then one coalesced
// gmem atomic pass per block.
__global__ void __launch_bounds__(128, 5)
k_pass(const float* __restrict__ u, int which) {
    float* p = (which == 0) ? g_p1 : g_p2;
    int b = blockIdx.y;
    int blk = blockIdx.x;                  // 0..31 -> 64 rows each
    __shared__ float sv[J_*K_];
    __shared__ float ps[J_*K_];
    for (int i = threadIdx.x; i < J_*K_; i += 128) {
        sv[i] = g_v[b*J_*K_ + i];
        ps[i] = 0.f;
    }
    __syncthreads();

    int warp = threadIdx.x >> 5, lane = threadIdx.x & 31;
    int q = lane >> 3, s = lane & 7;
    int rowbase = blk*64 + warp*16;
    const float* ub = u + (size_t)b*N_*K_;

    u64 p2[J_][2];
#pragma unroll
    for (int j = 0; j < J_; j++) { p2[j][0] = 0ULL; p2[j][1] = 0ULL; }

#pragma unroll 1
    for (int it = 0; it < 4; it++) {
        int r0 = rowbase + it*4;
        // dot-phase loads: own row (r0+q), 16 floats strided as 4 x float4
        const float4* urow = (const float4*)(ub + (size_t)(r0 + q)*K_);
        float4 d0 = urow[0*8 + s];
        float4 d1 = urow[1*8 + s];
        float4 d2 = urow[2*8 + s];
        float4 d3 = urow[3*8 + s];
        // accum-phase loads, lane-relative row order (r -> row q^r)
        u64 up01[4], up23[4];
#pragma unroll
        for (int r = 0; r < 4; r++) {
            const float* rp = ub + (size_t)(r0 + (q ^ r))*K_ + lane;
            float e0 = rp[0], e1 = rp[32], e2 = rp[64], e3 = rp[96];
            up01[r] = pack2(e0, e1);
            up23[r] = pack2(e2, e3);
        }

        float pd[J_];
#pragma unroll
        for (int j = 0; j < J_; j++) {
            const float4* vj = (const float4*)(sv + j*K_);
            float4 v0 = vj[0*8 + s];
            float4 v1 = vj[1*8 + s];
            float4 v2 = vj[2*8 + s];
            float4 v3 = vj[3*8 + s];
            u64 aA = ffma2(f4lo(d0), f4lo(v0), 0ULL);
            u64 aB = ffma2(f4hi(d0), f4hi(v0), 0ULL);
            aA = ffma2(f4lo(d1), f4lo(v1), aA);
            aB = ffma2(f4hi(d1), f4hi(v1), aB);
            aA = ffma2(f4lo(d2), f4lo(v2), aA);
            aB = ffma2(f4hi(d2), f4hi(v2), aB);
            aA = ffma2(f4lo(d3), f4lo(v3), aA);
            aB = ffma2(f4hi(d3), f4hi(v3), aB);
            float2 fa = unpack2(aA), fb = unpack2(aB);
            pd[j] = (fa.x + fa.y) + (fb.x + fb.y);
        }
        // reduce across the 8 lanes owning this row (3 levels)
#pragma unroll
        for (int m = 4; m >= 1; m >>= 1) {
#pragma unroll
            for (int j = 0; j < J_; j++)
                pd[j] += __shfl_xor_sync(0xffffffffu, pd[j], m);
        }
        // softmax over j (each lane has its own row's full dots)
        float m01 = fmaxf(pd[0], pd[1]), m23 = fmaxf(pd[2], pd[3]);
        float m45 = fmaxf(pd[4], pd[5]), m67 = fmaxf(pd[6], pd[7]);
        float m89 = fmaxf(pd[8], pd[9]);
        float mx = fmaxf(fmaxf(fmaxf(m01, m23), fmaxf(m45, m67)), m89);
        float Z = 0.f;
#pragma unroll
        for (int j = 0; j < J_; j++) { pd[j] = __expf(pd[j] - mx); Z += pd[j]; }
        float rZ = __fdividef(1.0f, Z);
        // accumulate all 4 rows: coefficient of row q^r arrives via shfl_xor(r*8)
#pragma unroll
        for (int j = 0; j < J_; j++) {
            float c0 = pd[j] * rZ;
            float c1 = __shfl_xor_sync(0xffffffffu, c0, 8);
            float c2 = __shfl_xor_sync(0xffffffffu, c0, 16);
            float c3 = __shfl_xor_sync(0xffffffffu, c0, 24);
            u64 cc;
            cc = pack2(c0, c0);
            p2[j][0] = ffma2(cc, up01[0], p2[j][0]);
            p2[j][1] = ffma2(cc, up23[0], p2[j][1]);
            cc = pack2(c1, c1);
            p2[j][0] = ffma2(cc, up01[1], p2[j][0]);
            p2[j][1] = ffma2(cc, up23[1], p2[j][1]);
            cc = pack2(c2, c2);
            p2[j][0] = ffma2(cc, up01[2], p2[j][0]);
            p2[j][1] = ffma2(cc, up23[2], p2[j][1]);
            cc = pack2(c3, c3);
            p2[j][0] = ffma2(cc, up01[3], p2[j][0]);
            p2[j][1] = ffma2(cc, up23[3], p2[j][1]);
        }
    }

    // dump register accumulators into block-shared buffer (conflict-free)
#pragma unroll
    for (int j = 0; j < J_; j++) {
        float2 x0 = unpack2(p2[j][0]);   // k = lane, 32+lane
        float2 x1 = unpack2(p2[j][1]);   // k = 64+lane, 96+lane
        atomicAdd(&ps[j*K_ +       lane], x0.x);
        atomicAdd(&ps[j*K_ +  32 + lane], x0.y);
        atomicAdd(&ps[j*K_ +  64 + lane], x1.x);
        atomicAdd(&ps[j*K_ +  96 + lane], x1.y);
    }
    __syncthreads();
    // one coalesced gmem-atomic pass per block
    float* pb = p + b*J_*K_;
    for (int i = threadIdx.x; i < J_*K_; i += 128)
        atomicAdd(pb + i, ps[i]);
}

// o2[b,j,d] = sum_k p2[b,j,k]*W[k,jd]; out = squash(o2) over d
__global__ void k_final(const float* __restrict__ W, float* __restrict__ out) {
    int b = blockIdx.x, t = threadIdx.x;   // 160 threads
    int j = t >> 4;
    __shared__ float so[F_];
    const float* pj = g_p2 + b*J_*K_ + j*K_;
    const float* wcol = W + t;
    float acc = 0.f;
#pragma unroll 8
    for (int k = 0; k < K_; k++) acc += pj[k] * wcol[k*F_];
    so[t] = acc;
    __syncthreads();
    float s2 = 0.f;
#pragma unroll
    for (int d2 = 0; d2 < D_; d2++) { float x = so[j*D_ + d2]; s2 += x*x; }
    out[b*F_ + t] = acc * s2 / ((1.f + s2) * sqrtf(s2 + 1e-7f));
}

extern "C" void kernel_launch(void* const* d_in, const int* in_sizes, int n_in,
                              void* d_out, int out_size) {
    const float* u = (const float*)d_in[0];
    const float* W = (const float*)d_in[1];
    float* out = (float*)d_out;

    k_init<<<(B_*J_*K_ + 255)/256, 256>>>();
    k_sum<<<dim3(8, B_), 256>>>(u);
    k_ov<<<B_, F_>>>(W, 0);                  // o0 (c uniform), v1
    k_pass<<<dim3(32, B_), 128>>>(u, 0);     // b1 -> softmax -> p1
    k_ov<<<B_, F_>>>(W, 1);                  // o1, v2
    k_pass<<<dim3(32, B_), 128>>>(u, 1);     // b2 -> softmax -> p2
    k_final<<<B_, F_>>>(W, out);             // o2 -> squash
}

// round 4
// speedup vs baseline: 1.8037x; 1.8037x over previous
#include <cuda_runtime.h>
#include <math.h>

#define B_  64
#define N_  2048
#define K_  128
#define J_  10
#define D_  16
#define F_  160   // J_*D_

typedef unsigned long long u64;

// scratch (device globals: no allocation allowed)
__device__ float g_s [B_*K_];        // sum over n of u
__device__ float g_v [B_*J_*K_];     // v[b,j,k] = sum_d W[k,jd]*o[b,j,d]
__device__ float g_p1[B_*J_*K_];     // p after routing iter 1
__device__ float g_p2[B_*J_*K_];     // p after routing iter 2

__device__ __forceinline__ u64 ffma2(u64 a, u64 b, u64 c) {
    u64 d; asm("fma.rn.f32x2 %0, %1, %2, %3;" : "=l"(d) : "l"(a), "l"(b), "l"(c));
    return d;
}
__device__ __forceinline__ u64 pack2(float x, float y) {
    u64 d; asm("mov.b64 %0, {%1, %2};" : "=l"(d) : "f"(x), "f"(y));
    return d;
}
__device__ __forceinline__ float2 unpack2(u64 v) {
    float2 r; asm("mov.b64 {%0, %1}, %2;" : "=f"(r.x), "=f"(r.y) : "l"(v));
    return r;
}

__global__ void k_init() {
    int i = blockIdx.x * blockDim.x + threadIdx.x;
    if (i < B_*K_) g_s[i] = 0.f;
    if (i < B_*J_*K_) { g_p1[i] = 0.f; g_p2[i] = 0.f; }
}

// s[b,k] = sum_n u[b,n,k]  (smem pre-reduction, 1 atomic per k per block)
__global__ void k_sum(const float* __restrict__ u) {
    int b = blockIdx.y;
    int chunk = blockIdx.x;            // 0..7, 256 rows each
    int k4 = threadIdx.x & 31;         // float4 index within row
    int rg = threadIdx.x >> 5;         // 0..7, 32 rows each
    const float4* up = (const float4*)(u + ((size_t)b*N_ + (size_t)chunk*256 + (size_t)rg*32)*K_);
    float4 acc = make_float4(0.f,0.f,0.f,0.f);
#pragma unroll 8
    for (int r = 0; r < 32; r++) {
        float4 t = up[r*32 + k4];
        acc.x += t.x; acc.y += t.y; acc.z += t.z; acc.w += t.w;
    }
    __shared__ float4 sred[8][32];
    sred[rg][k4] = acc;
    __syncthreads();
    if (rg == 0) {
#pragma unroll
        for (int i = 1; i < 8; i++) {
            float4 t = sred[i][k4];
            acc.x += t.x; acc.y += t.y; acc.z += t.z; acc.w += t.w;
        }
        float* sp = g_s + b*K_ + k4*4;
        atomicAdd(sp+0, acc.x); atomicAdd(sp+1, acc.y);
        atomicAdd(sp+2, acc.z); atomicAdd(sp+3, acc.w);
    }
}

// mode 0: o[b,j,d] = 0.1 * sum_k s[b,k]   * W[k, j*16+d]   (uses g_s)
// mode 1: o[b,j,d] =       sum_k p1[b,j,k]* W[k, j*16+d]   (uses g_p1)
// then    v[b,j,k] = sum_d o[b,j,d] * W[k, j*16+d]
__global__ void k_ov(const float* __restrict__ W, int mode) {
    int b = blockIdx.x, t = threadIdx.x;   // 160 threads
    __shared__ float src[J_*K_];
    __shared__ float so[F_];
    if (mode == 0) {
        if (t < K_) src[t] = g_s[b*K_ + t];
    } else {
        for (int i = t; i < J_*K_; i += F_) src[i] = g_p1[b*J_*K_ + i];
    }
    __syncthreads();
    int j = t >> 4;
    float acc = 0.f;
    const float* wcol = W + t;             // W[k*F_ + t]
    if (mode == 0) {
#pragma unroll 8
        for (int k = 0; k < K_; k++) acc += src[k] * wcol[k*F_];
        acc *= 0.1f;
    } else {
        const float* pj = src + j*K_;
#pragma unroll 8
        for (int k = 0; k < K_; k++) acc += pj[k] * wcol[k*F_];
    }
    so[t] = acc;
    __syncthreads();
    for (int e = t; e < J_*K_; e += F_) {
        int jj = e >> 7, k = e & 127;
        const float* wrow = W + k*F_ + jj*D_;
        const float* oj = so + jj*D_;
        float v = 0.f;
#pragma unroll
        for (int d2 = 0; d2 < D_; d2++) v += oj[d2] * wrow[d2];
        g_v[b*J_*K_ + e] = v;
    }
}

// fused: b[j] = u_row . v[j]  -> softmax over j -> p[j,:] += c[j]*u_row
// Full warp per row: lane owns k = 4*lane..4*lane+3.
//  - one LDG.128 per row (u read ONCE per pass)
//  - v held in registers (loaded once per block, no LDS in loop)
//  - 5-level butterfly for the 10 dots; softmax replicated in all lanes
//  - p accumulated in registers over the lane's own k-slice: no coefficient
//    shuffles, no cross-lane fold; smem aggregation + 1 gmem atomic pass.
__global__ void __launch_bounds__(256, 2)
k_pass(const float* __restrict__ u, int which) {
    float* p = (which == 0) ? g_p1 : g_p2;
    int b = blockIdx.y;
    int blk = blockIdx.x;                  // 0..31 -> 64 rows each
    int tid = threadIdx.x;
    int warp = tid >> 5, lane = tid & 31;

    __shared__ float ps[J_*K_];
    for (int i = tid; i < J_*K_; i += 256) ps[i] = 0.f;

    // v[j] slice for this lane (k = 4*lane..4*lane+3), kept in registers
    u64 v0[J_], v1[J_];
    {
        const float4* vb = (const float4*)(g_v + b*J_*K_);
#pragma unroll
        for (int j = 0; j < J_; j++) {
            float4 t = vb[j*32 + lane];
            v0[j] = pack2(t.x, t.y);
            v1[j] = pack2(t.z, t.w);
        }
    }
    __syncthreads();

    u64 p20[J_], p21[J_];
#pragma unroll
    for (int j = 0; j < J_; j++) { p20[j] = 0ULL; p21[j] = 0ULL; }

    const float4* ub = (const float4*)(u + ((size_t)b*N_ + (size_t)blk*64)*K_);

    // prefetch first row
    float4 t = ub[(size_t)warp*32 + lane];

#pragma unroll 1
    for (int r8 = 0; r8 < 8; r8++) {
        u64 u0 = pack2(t.x, t.y);
        u64 u1 = pack2(t.z, t.w);
        // prefetch next row (row = (r8+1)*8 + warp) while we crunch this one
        if (r8 < 7) t = ub[(size_t)((r8+1)*8 + warp)*32 + lane];

        float pd[J_];
#pragma unroll
        for (int j = 0; j < J_; j++) {
            u64 acc = ffma2(u0, v0[j], ffma2(u1, v1[j], 0ULL));
            float2 f = unpack2(acc);
            pd[j] = f.x + f.y;
        }
        // reduce across all 32 lanes (5 levels)
#pragma unroll
        for (int m = 16; m >= 1; m >>= 1) {
#pragma unroll
            for (int j = 0; j < J_; j++)
                pd[j] += __shfl_xor_sync(0xffffffffu, pd[j], m);
        }
        // softmax over j (replicated in all lanes)
        float m01 = fmaxf(pd[0], pd[1]), m23 = fmaxf(pd[2], pd[3]);
        float m45 = fmaxf(pd[4], pd[5]), m67 = fmaxf(pd[6], pd[7]);
        float m89 = fmaxf(pd[8], pd[9]);
        float mx = fmaxf(fmaxf(fmaxf(m01, m23), fmaxf(m45, m67)), m89);
        float Z = 0.f;
#pragma unroll
        for (int j = 0; j < J_; j++) { pd[j] = __expf(pd[j] - mx); Z += pd[j]; }
        float rZ = __fdividef(1.0f, Z);
        // accumulate into this lane's k-slice
#pragma unroll
        for (int j = 0; j < J_; j++) {
            float c = pd[j] * rZ;
            u64 cc = pack2(c, c);
            p20[j] = ffma2(cc, u0, p20[j]);
            p21[j] = ffma2(cc, u1, p21[j]);
        }
    }

    // aggregate across the 8 warps of this block (smem atomics, then 1 gmem pass)
#pragma unroll
    for (int j = 0; j < J_; j++) {
        float2 a = unpack2(p20[j]);
        float2 c = unpack2(p21[j]);
        float* d = ps + j*K_ + lane*4;
        atomicAdd(d+0, a.x); atomicAdd(d+1, a.y);
        atomicAdd(d+2, c.x); atomicAdd(d+3, c.y);
    }
    __syncthreads();
    float* pb = p + b*J_*K_;
    for (int i = tid; i < J_*K_; i += 256)
        atomicAdd(pb + i, ps[i]);
}

// o2[b,j,d] = sum_k p2[b,j,k]*W[k,jd]; out = squash(o2) over d
__global__ void k_final(const float* __restrict__ W, float* __restrict__ out) {
    int b = blockIdx.x, t = threadIdx.x;   // 160 threads
    int j = t >> 4;
    __shared__ float so[F_];
    const float* pj = g_p2 + b*J_*K_ + j*K_;
    const float* wcol = W + t;
    float acc = 0.f;
#pragma unroll 8
    for (int k = 0; k < K_; k++) acc += pj[k] * wcol[k*F_];
    so[t] = acc;
    __syncthreads();
    float s2 = 0.f;
#pragma unroll
    for (int d2 = 0; d2 < D_; d2++) { float x = so[j*D_ + d2]; s2 += x*x; }
    out[b*F_ + t] = acc * s2 / ((1.f + s2) * sqrtf(s2 + 1e-7f));
}

extern "C" void kernel_launch(void* const* d_in, const int* in_sizes, int n_in,
                              void* d_out, int out_size) {
    const float* u = (const float*)d_in[0];
    const float* W = (const float*)d_in[1];
    float* out = (float*)d_out;

    k_init<<<(B_*J_*K_ + 255)/256, 256>>>();
    k_sum<<<dim3(8, B_), 256>>>(u);
    k_ov<<<B_, F_>>>(W, 0);                  // o0 (c uniform), v1
    k_pass<<<dim3(32, B_), 256>>>(u, 0);     // b1 -> softmax -> p1
    k_ov<<<B_, F_>>>(W, 1);                  // o1, v2
    k_pass<<<dim3(32, B_), 256>>>(u, 1);     // b2 -> softmax -> p2
    k_final<<<B_, F_>>>(W, out);             // o2 -> squash
}

// round 6
// speedup vs baseline: 1.9860x; 1.1011x over previous
#include <cuda_runtime.h>
#include <math.h>

#define B_  64
#define N_  2048
#define K_  128
#define J_  10
#define D_  16
#define F_  160   // J_*D_

typedef unsigned long long u64;

// scratch (device globals: no allocation allowed)
__device__ float g_s [B_*K_];        // sum over n of u
__device__ float g_v [B_*J_*K_];     // v[b,j,k] = sum_d W[k,jd]*o[b,j,d]
__device__ float g_p1[B_*J_*K_];     // p after routing iter 1
__device__ float g_p2[B_*J_*K_];     // p after routing iter 2

__device__ __forceinline__ u64 ffma2(u64 a, u64 b, u64 c) {
    u64 d; asm("fma.rn.f32x2 %0, %1, %2, %3;" : "=l"(d) : "l"(a), "l"(b), "l"(c));
    return d;
}
__device__ __forceinline__ u64 pack2(float x, float y) {
    u64 d; asm("mov.b64 %0, {%1, %2};" : "=l"(d) : "f"(x), "f"(y));
    return d;
}
__device__ __forceinline__ float2 unpack2(u64 v) {
    float2 r; asm("mov.b64 {%0, %1}, %2;" : "=f"(r.x), "=f"(r.y) : "l"(v));
    return r;
}

__global__ void k_init() {
    int i = blockIdx.x * blockDim.x + threadIdx.x;
    if (i < B_*K_) g_s[i] = 0.f;
    if (i < B_*J_*K_) { g_p1[i] = 0.f; g_p2[i] = 0.f; }
}

// s[b,k] = sum_n u[b,n,k]  (smem pre-reduction, 1 atomic per k per block)
__global__ void k_sum(const float* __restrict__ u) {
    int b = blockIdx.y;
    int chunk = blockIdx.x;            // 0..7, 256 rows each
    int k4 = threadIdx.x & 31;         // float4 index within row
    int rg = threadIdx.x >> 5;         // 0..7, 32 rows each
    const float4* up = (const float4*)(u + ((size_t)b*N_ + (size_t)chunk*256 + (size_t)rg*32)*K_);
    float4 acc = make_float4(0.f,0.f,0.f,0.f);
#pragma unroll 8
    for (int r = 0; r < 32; r++) {
        float4 t = up[r*32 + k4];
        acc.x += t.x; acc.y += t.y; acc.z += t.z; acc.w += t.w;
    }
    __shared__ float4 sred[8][32];
    sred[rg][k4] = acc;
    __syncthreads();
    if (rg == 0) {
#pragma unroll
        for (int i = 1; i < 8; i++) {
            float4 t = sred[i][k4];
            acc.x += t.x; acc.y += t.y; acc.z += t.z; acc.w += t.w;
        }
        float* sp = g_s + b*K_ + k4*4;
        atomicAdd(sp+0, acc.x); atomicAdd(sp+1, acc.y);
        atomicAdd(sp+2, acc.z); atomicAdd(sp+3, acc.w);
    }
}

// mode 0: o[b,j,d] = 0.1 * sum_k s[b,k]   * W[k, j*16+d]   (uses g_s)
// mode 1: o[b,j,d] =       sum_k p1[b,j,k]* W[k, j*16+d]   (uses g_p1)
// then    v[b,j,k] = sum_d o[b,j,d] * W[k, j*16+d]
__global__ void k_ov(const float* __restrict__ W, int mode) {
    int b = blockIdx.x, t = threadIdx.x;   // 160 threads
    __shared__ float src[J_*K_];
    __shared__ float so[F_];
    if (mode == 0) {
        if (t < K_) src[t] = g_s[b*K_ + t];
    } else {
        for (int i = t; i < J_*K_; i += F_) src[i] = g_p1[b*J_*K_ + i];
    }
    __syncthreads();
    int j = t >> 4;
    float acc = 0.f;
    const float* wcol = W + t;             // W[k*F_ + t]
    if (mode == 0) {
#pragma unroll 8
        for (int k = 0; k < K_; k++) acc += src[k] * wcol[k*F_];
        acc *= 0.1f;
    } else {
        const float* pj = src + j*K_;
#pragma unroll 8
        for (int k = 0; k < K_; k++) acc += pj[k] * wcol[k*F_];
    }
    so[t] = acc;
    __syncthreads();
    for (int e = t; e < J_*K_; e += F_) {
        int jj = e >> 7, k = e & 127;
        const float* wrow = W + k*F_ + jj*D_;
        const float* oj = so + jj*D_;
        float v = 0.f;
#pragma unroll
        for (int d2 = 0; d2 < D_; d2++) v += oj[d2] * wrow[d2];
        g_v[b*J_*K_ + e] = v;
    }
}

// fused: b[j] = u_row . v[j]  -> softmax over j -> p[j,:] += c[j]*u_row
// Warp processes 2 rows per iteration; lane owns k = 4*lane..4*lane+3.
//  - one LDG.128 per row (u read ONCE per pass)
//  - v held in registers (loaded once per block, no LDS in loop)
//  - butterfly level 16 doubles as a ROW SPLIT: lanes 0-15 end owning row A's
//    dots, 16-31 row B's -> only 4 more levels x 10 j, and softmax runs once
//    per 2 rows (halves the shfl+MUFU work per row vs R4)
//  - coefficients swapped across halves via shfl_xor(16); p accumulated in
//    registers over the lane's own k-slice; smem aggregation + 1 gmem pass.
__global__ void __launch_bounds__(256, 2)
k_pass(const float* __restrict__ u, int which) {
    float* p = (which == 0) ? g_p1 : g_p2;
    int b = blockIdx.y;
    int blk = blockIdx.x;                  // 0..31 -> 64 rows each
    int tid = threadIdx.x;
    int warp = tid >> 5, lane = tid & 31;
    int half = lane >> 4;

    __shared__ float ps[J_*K_];
    for (int i = tid; i < J_*K_; i += 256) ps[i] = 0.f;

    // v[j] slice for this lane (k = 4*lane..4*lane+3), kept in registers
    u64 v0[J_], v1[J_];
    {
        const float4* vb = (const float4*)(g_v + b*J_*K_);
#pragma unroll
        for (int j = 0; j < J_; j++) {
            float4 t = vb[j*32 + lane];
            v0[j] = pack2(t.x, t.y);
            v1[j] = pack2(t.z, t.w);
        }
    }
    __syncthreads();

    u64 p20[J_], p21[J_];
#pragma unroll
    for (int j = 0; j < J_; j++) { p20[j] = 0ULL; p21[j] = 0ULL; }

    const float4* ub = (const float4*)(u + ((size_t)b*N_ + (size_t)blk*64)*K_);

    // prefetch first row pair (rows warp*2, warp*2+1)
    float4 tA = ub[(size_t)(warp*2    )*32 + lane];
    float4 tB = ub[(size_t)(warp*2 + 1)*32 + lane];

#pragma unroll 1
    for (int it = 0; it < 4; it++) {
        u64 a0 = pack2(tA.x, tA.y), a1 = pack2(tA.z, tA.w);
        u64 b0 = pack2(tB.x, tB.y), b1 = pack2(tB.z, tB.w);
        if (it < 3) {   // prefetch next row pair
            tA = ub[(size_t)((it+1)*16 + warp*2    )*32 + lane];
            tB = ub[(size_t)((it+1)*16 + warp*2 + 1)*32 + lane];
        }

        // dot partials for both rows; level-16 exchange = row split
        float pd[J_];
#pragma unroll
        for (int j = 0; j < J_; j++) {
            u64 accA = ffma2(a0, v0[j], ffma2(a1, v1[j], 0ULL));
            u64 accB = ffma2(b0, v0[j], ffma2(b1, v1[j], 0ULL));
            float2 fa = unpack2(accA), fb = unpack2(accB);
            float sA = fa.x + fa.y;
            float sB = fb.x + fb.y;
            // send the partial the partner half needs; keep own row's partial
            float x = half ? sA : sB;
            float t = __shfl_xor_sync(0xffffffffu, x, 16);
            pd[j] = (half ? sB : sA) + t;
        }
        // remaining 4 butterfly levels (xor preserves bit 16 -> stays in-row)
#pragma unroll
        for (int m = 8; m >= 1; m >>= 1) {
#pragma unroll
            for (int j = 0; j < J_; j++)
                pd[j] += __shfl_xor_sync(0xffffffffu, pd[j], m);
        }
        // softmax over j (each half-warp: its own row)
        float m01 = fmaxf(pd[0], pd[1]), m23 = fmaxf(pd[2], pd[3]);
        float m45 = fmaxf(pd[4], pd[5]), m67 = fmaxf(pd[6], pd[7]);
        float m89 = fmaxf(pd[8], pd[9]);
        float mx = fmaxf(fmaxf(fmaxf(m01, m23), fmaxf(m45, m67)), m89);
        float Z = 0.f;
#pragma unroll
        for (int j = 0; j < J_; j++) { pd[j] = __expf(pd[j] - mx); Z += pd[j]; }
        float rZ = __fdividef(1.0f, Z);
        // accumulate both rows into this lane's k-slice
#pragma unroll
        for (int j = 0; j < J_; j++) {
            float cOwn = pd[j] * rZ;
            float cOth = __shfl_xor_sync(0xffffffffu, cOwn, 16);
            float cA = half ? cOth : cOwn;
            float cB = half ? cOwn : cOth;
            u64 ccA = pack2(cA, cA);
            u64 ccB = pack2(cB, cB);
            p20[j] = ffma2(ccA, a0, p20[j]);
            p21[j] = ffma2(ccA, a1, p21[j]);
            p20[j] = ffma2(ccB, b0, p20[j]);
            p21[j] = ffma2(ccB, b1, p21[j]);
        }
    }

    // aggregate across the 8 warps of this block (smem atomics, then 1 gmem pass)
#pragma unroll
    for (int j = 0; j < J_; j++) {
        float2 a = unpack2(p20[j]);
        float2 c = unpack2(p21[j]);
        float* d = ps + j*K_ + lane*4;
        atomicAdd(d+0, a.x); atomicAdd(d+1, a.y);
        atomicAdd(d+2, c.x); atomicAdd(d+3, c.y);
    }
    __syncthreads();
    float* pb = p + b*J_*K_;
    for (int i = tid; i < J_*K_; i += 256)
        atomicAdd(pb + i, ps[i]);
}

// o2[b,j,d] = sum_k p2[b,j,k]*W[k,jd]; out = squash(o2) over d
__global__ void k_final(const float* __restrict__ W, float* __restrict__ out) {
    int b = blockIdx.x, t = threadIdx.x;   // 160 threads
    int j = t >> 4;
    __shared__ float so[F_];
    const float* pj = g_p2 + b*J_*K_ + j*K_;
    const float* wcol = W + t;
    float acc = 0.f;
#pragma unroll 8
    for (int k = 0; k < K_; k++) acc += pj[k] * wcol[k*F_];
    so[t] = acc;
    __syncthreads();
    float s2 = 0.f;
#pragma unroll
    for (int d2 = 0; d2 < D_; d2++) { float x = so[j*D_ + d2]; s2 += x*x; }
    out[b*F_ + t] = acc * s2 / ((1.f + s2) * sqrtf(s2 + 1e-7f));
}

extern "C" void kernel_launch(void* const* d_in, const int* in_sizes, int n_in,
                              void* d_out, int out_size) {
    const float* u = (const float*)d_in[0];
    const float* W = (const float*)d_in[1];
    float* out = (float*)d_out;

    k_init<<<(B_*J_*K_ + 255)/256, 256>>>();
    k_sum<<<dim3(8, B_), 256>>>(u);
    k_ov<<<B_, F_>>>(W, 0);                  // o0 (c uniform), v1
    k_pass<<<dim3(32, B_), 256>>>(u, 0);     // b1 -> softmax -> p1
    k_ov<<<B_, F_>>>(W, 1);                  // o1, v2
    k_pass<<<dim3(32, B_), 256>>>(u, 1);     // b2 -> softmax -> p2
    k_final<<<B_, F_>>>(W, out);             // o2 -> squash
}

// round 7
// speedup vs baseline: 2.1442x; 1.0797x over previous
#include <cuda_runtime.h>
#include <math.h>

#define B_  64
#define N_  2048
#define K_  128
#define J_  10
#define D_  16
#define F_  160   // J_*D_
#define CS_ 12    // padded c row stride (48B, 16B-aligned)

typedef unsigned long long u64;

// scratch (device globals: no allocation allowed)
__device__ float g_s [B_*K_];        // sum over n of u
__device__ float g_v [B_*J_*K_];     // v[b,j,k] = sum_d W[k,jd]*o[b,j,d]
__device__ float g_c [B_*N_*CS_];    // softmax coefficients (padded to 12)
__device__ float g_p1[B_*J_*K_];     // p after routing iter 1
__device__ float g_p2[B_*J_*K_];     // p after routing iter 2

__device__ __forceinline__ u64 ffma2(u64 a, u64 b, u64 c) {
    u64 d; asm("fma.rn.f32x2 %0, %1, %2, %3;" : "=l"(d) : "l"(a), "l"(b), "l"(c));
    return d;
}
__device__ __forceinline__ u64 pack2(float x, float y) {
    u64 d; asm("mov.b64 %0, {%1, %2};" : "=l"(d) : "f"(x), "f"(y));
    return d;
}
__device__ __forceinline__ float2 unpack2(u64 v) {
    float2 r; asm("mov.b64 {%0, %1}, %2;" : "=f"(r.x), "=f"(r.y) : "l"(v));
    return r;
}

__global__ void k_init() {
    int i = blockIdx.x * blockDim.x + threadIdx.x;
    if (i < B_*K_) g_s[i] = 0.f;
    if (i < B_*J_*K_) { g_p1[i] = 0.f; g_p2[i] = 0.f; }
}

// s[b,k] = sum_n u[b,n,k]  (smem pre-reduction, 1 atomic per k per block)
__global__ void k_sum(const float* __restrict__ u) {
    int b = blockIdx.y;
    int chunk = blockIdx.x;            // 0..7, 256 rows each
    int k4 = threadIdx.x & 31;
    int rg = threadIdx.x >> 5;
    const float4* up = (const float4*)(u + ((size_t)b*N_ + (size_t)chunk*256 + (size_t)rg*32)*K_);
    float4 acc = make_float4(0.f,0.f,0.f,0.f);
#pragma unroll 8
    for (int r = 0; r < 32; r++) {
        float4 t = up[r*32 + k4];
        acc.x += t.x; acc.y += t.y; acc.z += t.z; acc.w += t.w;
    }
    __shared__ float4 sred[8][32];
    sred[rg][k4] = acc;
    __syncthreads();
    if (rg == 0) {
#pragma unroll
        for (int i = 1; i < 8; i++) {
            float4 t = sred[i][k4];
            acc.x += t.x; acc.y += t.y; acc.z += t.z; acc.w += t.w;
        }
        float* sp = g_s + b*K_ + k4*4;
        atomicAdd(sp+0, acc.x); atomicAdd(sp+1, acc.y);
        atomicAdd(sp+2, acc.z); atomicAdd(sp+3, acc.w);
    }
}

// mode 0: o[b,j,d] = 0.1 * sum_k s[b,k]   * W[k, j*16+d]
// mode 1: o[b,j,d] =       sum_k p1[b,j,k]* W[k, j*16+d]
// then    v[b,j,k] = sum_d o[b,j,d] * W[k, j*16+d]
__global__ void k_ov(const float* __restrict__ W, int mode) {
    int b = blockIdx.x, t = threadIdx.x;   // 160 threads
    __shared__ float src[J_*K_];
    __shared__ float so[F_];
    if (mode == 0) {
        if (t < K_) src[t] = g_s[b*K_ + t];
    } else {
        for (int i = t; i < J_*K_; i += F_) src[i] = g_p1[b*J_*K_ + i];
    }
    __syncthreads();
    int j = t >> 4;
    float acc = 0.f;
    const float* wcol = W + t;
    if (mode == 0) {
#pragma unroll 8
        for (int k = 0; k < K_; k++) acc += src[k] * wcol[k*F_];
        acc *= 0.1f;
    } else {
        const float* pj = src + j*K_;
#pragma unroll 8
        for (int k = 0; k < K_; k++) acc += pj[k] * wcol[k*F_];
    }
    so[t] = acc;
    __syncthreads();
    for (int e = t; e < J_*K_; e += F_) {
        int jj = e >> 7, k = e & 127;
        const float* wrow = W + k*F_ + jj*D_;
        const float* oj = so + jj*D_;
        float v = 0.f;
#pragma unroll
        for (int d2 = 0; d2 < D_; d2++) v += oj[d2] * wrow[d2];
        g_v[b*J_*K_ + e] = v;
    }
}

// k_dot: b[j] = u_row . v[j] -> softmax -> store c[b,n,12]
// Warp: 2 rows per iter, 32 rows total. Lane owns k = 4*lane..4*lane+3.
// v in registers; level-16 butterfly doubles as row split; each half-warp
// computes its row's softmax and lane (l&15)==0 stores the 10 coefficients.
// No accumulators, no smem, no block sync -> high occupancy.
__global__ void __launch_bounds__(256, 3)
k_dot(const float* __restrict__ u) {
    int b = blockIdx.x >> 3;
    int seg = blockIdx.x & 7;              // 256 rows per block
    int tid = threadIdx.x;
    int warp = tid >> 5, lane = tid & 31;
    int half = lane >> 4;

    u64 v0[J_], v1[J_];
    {
        const float4* vb = (const float4*)(g_v + b*J_*K_);
#pragma unroll
        for (int j = 0; j < J_; j++) {
            float4 t = vb[j*32 + lane];
            v0[j] = pack2(t.x, t.y);
            v1[j] = pack2(t.z, t.w);
        }
    }

    const float4* ub = (const float4*)(u + ((size_t)b*N_ + (size_t)seg*256)*K_);
    float* cb = g_c + ((size_t)b*N_ + (size_t)seg*256)*CS_;

    float4 tA = ub[(size_t)(warp*32    )*32 + lane];
    float4 tB = ub[(size_t)(warp*32 + 1)*32 + lane];

#pragma unroll 1
    for (int it = 0; it < 16; it++) {
        u64 a0 = pack2(tA.x, tA.y), a1 = pack2(tA.z, tA.w);
        u64 b0 = pack2(tB.x, tB.y), b1 = pack2(tB.z, tB.w);
        if (it < 15) {
            tA = ub[(size_t)(warp*32 + (it+1)*2    )*32 + lane];
            tB = ub[(size_t)(warp*32 + (it+1)*2 + 1)*32 + lane];
        }

        float pd[J_];
#pragma unroll
        for (int j = 0; j < J_; j++) {
            u64 accA = ffma2(a0, v0[j], ffma2(a1, v1[j], 0ULL));
            u64 accB = ffma2(b0, v0[j], ffma2(b1, v1[j], 0ULL));
            float2 fa = unpack2(accA), fb = unpack2(accB);
            float sA = fa.x + fa.y;
            float sB = fb.x + fb.y;
            float x = half ? sA : sB;
            float t = __shfl_xor_sync(0xffffffffu, x, 16);
            pd[j] = (half ? sB : sA) + t;
        }
#pragma unroll
        for (int m = 8; m >= 1; m >>= 1) {
#pragma unroll
            for (int j = 0; j < J_; j++)
                pd[j] += __shfl_xor_sync(0xffffffffu, pd[j], m);
        }
        float m01 = fmaxf(pd[0], pd[1]), m23 = fmaxf(pd[2], pd[3]);
        float m45 = fmaxf(pd[4], pd[5]), m67 = fmaxf(pd[6], pd[7]);
        float m89 = fmaxf(pd[8], pd[9]);
        float mx = fmaxf(fmaxf(fmaxf(m01, m23), fmaxf(m45, m67)), m89);
        float Z = 0.f;
#pragma unroll
        for (int j = 0; j < J_; j++) { pd[j] = __expf(pd[j] - mx); Z += pd[j]; }
        float rZ = __fdividef(1.0f, Z);
        // one lane per half-warp stores its row's 10 coefficients
        if ((lane & 15) == 0) {
            float* dst = cb + (size_t)(warp*32 + it*2 + half)*CS_;
            *(float4*)(dst    ) = make_float4(pd[0]*rZ, pd[1]*rZ, pd[2]*rZ, pd[3]*rZ);
            *(float4*)(dst + 4) = make_float4(pd[4]*rZ, pd[5]*rZ, pd[6]*rZ, pd[7]*rZ);
            *(float2*)(dst + 8) = make_float2(pd[8]*rZ, pd[9]*rZ);
        }
    }
}

// k_acc: p[b,j,k] += sum_rows c[row,j] * u[row,k]
// Warp: 2 rows/iter, 32 rows total, lane owns k = 4*lane..4*lane+3.
// c read via uniform vector loads (broadcast). Zero shuffles, zero MUFU.
__global__ void __launch_bounds__(256, 3)
k_acc(const float* __restrict__ u, int which) {
    float* p = (which == 0) ? g_p1 : g_p2;
    int b = blockIdx.x >> 3;
    int seg = blockIdx.x & 7;              // 256 rows per block
    int tid = threadIdx.x;
    int warp = tid >> 5, lane = tid & 31;

    __shared__ float ps[J_*K_];
    for (int i = tid; i < J_*K_; i += 256) ps[i] = 0.f;
    __syncthreads();

    u64 p20[J_], p21[J_];
#pragma unroll
    for (int j = 0; j < J_; j++) { p20[j] = 0ULL; p21[j] = 0ULL; }

    const float4* ub = (const float4*)(u + ((size_t)b*N_ + (size_t)seg*256)*K_);
    const float* cb = g_c + ((size_t)b*N_ + (size_t)seg*256)*CS_;

#pragma unroll 2
    for (int it = 0; it < 16; it++) {
        int rA = warp*32 + it*2, rB = rA + 1;
        float4 uA = ub[(size_t)rA*32 + lane];
        float4 uB = ub[(size_t)rB*32 + lane];
        const float* cA = cb + (size_t)rA*CS_;
        const float* cB = cb + (size_t)rB*CS_;
        float4 cA0 = *(const float4*)(cA);
        float4 cA1 = *(const float4*)(cA + 4);
        float2 cA2 = *(const float2*)(cA + 8);
        float4 cB0 = *(const float4*)(cB);
        float4 cB1 = *(const float4*)(cB + 4);
        float2 cB2 = *(const float2*)(cB + 8);
        u64 a0 = pack2(uA.x, uA.y), a1 = pack2(uA.z, uA.w);
        u64 b0 = pack2(uB.x, uB.y), b1 = pack2(uB.z, uB.w);
        float ca[J_] = {cA0.x,cA0.y,cA0.z,cA0.w, cA1.x,cA1.y,cA1.z,cA1.w, cA2.x,cA2.y};
        float cbv[J_] = {cB0.x,cB0.y,cB0.z,cB0.w, cB1.x,cB1.y,cB1.z,cB1.w, cB2.x,cB2.y};
#pragma unroll
        for (int j = 0; j < J_; j++) {
            u64 ccA = pack2(ca[j], ca[j]);
            u64 ccB = pack2(cbv[j], cbv[j]);
            p20[j] = ffma2(ccA, a0, p20[j]);
            p21[j] = ffma2(ccA, a1, p21[j]);
            p20[j] = ffma2(ccB, b0, p20[j]);
            p21[j] = ffma2(ccB, b1, p21[j]);
        }
    }

    // aggregate the 8 warps via smem, then 1 coalesced gmem atomic pass
#pragma unroll
    for (int j = 0; j < J_; j++) {
        float2 a = unpack2(p20[j]);
        float2 c = unpack2(p21[j]);
        float* d = ps + j*K_ + lane*4;
        atomicAdd(d+0, a.x); atomicAdd(d+1, a.y);
        atomicAdd(d+2, c.x); atomicAdd(d+3, c.y);
    }
    __syncthreads();
    float* pb = p + b*J_*K_;
    for (int i = tid; i < J_*K_; i += 256)
        atomicAdd(pb + i, ps[i]);
}

// o2[b,j,d] = sum_k p2[b,j,k]*W[k,jd]; out = squash(o2) over d
__global__ void k_final(const float* __restrict__ W, float* __restrict__ out) {
    int b = blockIdx.x, t = threadIdx.x;   // 160 threads
    int j = t >> 4;
    __shared__ float so[F_];
    const float* pj = g_p2 + b*J_*K_ + j*K_;
    const float* wcol = W + t;
    float acc = 0.f;
#pragma unroll 8
    for (int k = 0; k < K_; k++) acc += pj[k] * wcol[k*F_];
    so[t] = acc;
    __syncthreads();
    float s2 = 0.f;
#pragma unroll
    for (int d2 = 0; d2 < D_; d2++) { float x = so[j*D_ + d2]; s2 += x*x; }
    out[b*F_ + t] = acc * s2 / ((1.f + s2) * sqrtf(s2 + 1e-7f));
}

extern "C" void kernel_launch(void* const* d_in, const int* in_sizes, int n_in,
                              void* d_out, int out_size) {
    const float* u = (const float*)d_in[0];
    const float* W = (const float*)d_in[1];
    float* out = (float*)d_out;

    k_init<<<(B_*J_*K_ + 255)/256, 256>>>();
    k_sum<<<dim3(8, B_), 256>>>(u);
    k_ov<<<B_, F_>>>(W, 0);          // o0 (c uniform), v1
    k_dot<<<512, 256>>>(u);          // b1 -> softmax -> c
    k_acc<<<512, 256>>>(u, 0);       // p1 = c^T u
    k_ov<<<B_, F_>>>(W, 1);          // o1, v2
    k_dot<<<512, 256>>>(u);          // b2 -> softmax -> c
    k_acc<<<512, 256>>>(u, 1);       // p2 = c^T u
    k_final<<<B_, F_>>>(W, out);     // o2 -> squash
}

// round 8
// speedup vs baseline: 2.7930x; 1.3026x over previous
#include <cuda_runtime.h>
#include <math.h>

#define B_  64
#define N_  2048
#define K_  128
#define J_  10
#define D_  16
#define F_  160   // J_*D_

typedef unsigned long long u64;

// scratch (device globals: no allocation allowed)
__device__ float g_s [B_*K_];        // sum over n of u
__device__ float g_v [B_*J_*K_];     // v[b,j,k] = sum_d W[k,jd]*o[b,j,d]
__device__ float g_p1[B_*J_*K_];     // p after routing iter 1
__device__ float g_p2[B_*J_*K_];     // p after routing iter 2

__device__ __forceinline__ u64 ffma2(u64 a, u64 b, u64 c) {
    u64 d; asm("fma.rn.f32x2 %0, %1, %2, %3;" : "=l"(d) : "l"(a), "l"(b), "l"(c));
    return d;
}
__device__ __forceinline__ u64 pack2(float x, float y) {
    u64 d; asm("mov.b64 %0, {%1, %2};" : "=l"(d) : "f"(x), "f"(y));
    return d;
}
__device__ __forceinline__ float2 unpack2(u64 v) {
    float2 r; asm("mov.b64 {%0, %1}, %2;" : "=f"(r.x), "=f"(r.y) : "l"(v));
    return r;
}

__global__ void k_init() {
    int i = blockIdx.x * blockDim.x + threadIdx.x;
    if (i < B_*K_) g_s[i] = 0.f;
    if (i < B_*J_*K_) { g_p1[i] = 0.f; g_p2[i] = 0.f; }
}

// s[b,k] = sum_n u[b,n,k]  (smem pre-reduction, 1 atomic per k per block)
__global__ void k_sum(const float* __restrict__ u) {
    int b = blockIdx.y;
    int chunk = blockIdx.x;            // 0..7, 256 rows each
    int k4 = threadIdx.x & 31;
    int rg = threadIdx.x >> 5;
    const float4* up = (const float4*)(u + ((size_t)b*N_ + (size_t)chunk*256 + (size_t)rg*32)*K_);
    float4 acc = make_float4(0.f,0.f,0.f,0.f);
#pragma unroll 8
    for (int r = 0; r < 32; r++) {
        float4 t = up[r*32 + k4];
        acc.x += t.x; acc.y += t.y; acc.z += t.z; acc.w += t.w;
    }
    __shared__ float4 sred[8][32];
    sred[rg][k4] = acc;
    __syncthreads();
    if (rg == 0) {
#pragma unroll
        for (int i = 1; i < 8; i++) {
            float4 t = sred[i][k4];
            acc.x += t.x; acc.y += t.y; acc.z += t.z; acc.w += t.w;
        }
        float* sp = g_s + b*K_ + k4*4;
        atomicAdd(sp+0, acc.x); atomicAdd(sp+1, acc.y);
        atomicAdd(sp+2, acc.z); atomicAdd(sp+3, acc.w);
    }
}

// mode 0: o[b,j,d] = 0.1 * sum_k s[b,k]   * W[k, j*16+d]
// mode 1: o[b,j,d] =       sum_k p1[b,j,k]* W[k, j*16+d]
// then    v[b,j,k] = sum_d o[b,j,d] * W[k, j*16+d]
__global__ void k_ov(const float* __restrict__ W, int mode) {
    int b = blockIdx.x, t = threadIdx.x;   // 160 threads
    __shared__ float src[J_*K_];
    __shared__ float so[F_];
    if (mode == 0) {
        if (t < K_) src[t] = g_s[b*K_ + t];
    } else {
        for (int i = t; i < J_*K_; i += F_) src[i] = g_p1[b*J_*K_ + i];
    }
    __syncthreads();
    int j = t >> 4;
    float acc = 0.f;
    const float* wcol = W + t;
    if (mode == 0) {
#pragma unroll 8
        for (int k = 0; k < K_; k++) acc += src[k] * wcol[k*F_];
        acc *= 0.1f;
    } else {
        const float* pj = src + j*K_;
#pragma unroll 8
        for (int k = 0; k < K_; k++) acc += pj[k] * wcol[k*F_];
    }
    so[t] = acc;
    __syncthreads();
    for (int e = t; e < J_*K_; e += F_) {
        int jj = e >> 7, k = e & 127;
        const float* wrow = W + k*F_ + jj*D_;
        const float* oj = so + jj*D_;
        float v = 0.f;
#pragma unroll
        for (int d2 = 0; d2 < D_; d2++) v += oj[d2] * wrow[d2];
        g_v[b*J_*K_ + e] = v;
    }
}

// fused pass: dots -> softmax -> p accumulation, 4 rows per warp-iteration.
// Lane owns k = 4*lane..4*lane+3; quarter q = lane>>3.
// u slots are loaded Q-RELATIVE: slot r = row r0 + (q^r). Then:
//   reduction: s0+=shfl16(s2); s1+=shfl16(s3); s0+=shfl8(s1); + 3 in-quarter
//   levels -> slot0 = full dot of row r0+q, replicated in the quarter.
//   softmax once per 4 rows (quarter-warp owns one row, same instr stream).
//   accumulation: coefficient for slot r is shfl_xor(c_own, 8*r) -- no selects.
// u is read from DRAM exactly once per pass.
__global__ void __launch_bounds__(256, 2)
k_pass(const float* __restrict__ u, int which) {
    float* p = (which == 0) ? g_p1 : g_p2;
    int b = blockIdx.x >> 3;
    int seg = blockIdx.x & 7;              // 256 rows per block
    int tid = threadIdx.x;
    int warp = tid >> 5, lane = tid & 31;
    int q = lane >> 3;

    __shared__ float ps[J_*K_];
    for (int i = tid; i < J_*K_; i += 256) ps[i] = 0.f;

    // v[j] slice for this lane (k = 4*lane..4*lane+3), kept in registers
    u64 v0[J_], v1[J_];
    {
        const float4* vb = (const float4*)(g_v + b*J_*K_);
#pragma unroll
        for (int j = 0; j < J_; j++) {
            float4 t = vb[j*32 + lane];
            v0[j] = pack2(t.x, t.y);
            v1[j] = pack2(t.z, t.w);
        }
    }
    __syncthreads();

    u64 p20[J_], p21[J_];
#pragma unroll
    for (int j = 0; j < J_; j++) { p20[j] = 0ULL; p21[j] = 0ULL; }

    const float4* ub = (const float4*)(u + ((size_t)b*N_ + (size_t)seg*256)*K_);

#pragma unroll 1
    for (int it = 0; it < 8; it++) {
        int r0 = warp*32 + it*4;
        // q-relative row loads: slot r holds row r0 + (q^r) at this lane's k
        u64 a0[4], a1[4];
#pragma unroll
        for (int r = 0; r < 4; r++) {
            float4 t = ub[(size_t)(r0 + (q ^ r))*32 + lane];
            a0[r] = pack2(t.x, t.y);
            a1[r] = pack2(t.z, t.w);
        }

        // dots + select-free split reduction
        float pd[J_];
#pragma unroll
        for (int j = 0; j < J_; j++) {
            float s0, s1, s2, s3;
            {
                u64 acc = ffma2(a0[0], v0[j], ffma2(a1[0], v1[j], 0ULL));
                float2 f = unpack2(acc); s0 = f.x + f.y;
            }
            {
                u64 acc = ffma2(a0[1], v0[j], ffma2(a1[1], v1[j], 0ULL));
                float2 f = unpack2(acc); s1 = f.x + f.y;
            }
            {
                u64 acc = ffma2(a0[2], v0[j], ffma2(a1[2], v1[j], 0ULL));
                float2 f = unpack2(acc); s2 = f.x + f.y;
            }
            {
                u64 acc = ffma2(a0[3], v0[j], ffma2(a1[3], v1[j], 0ULL));
                float2 f = unpack2(acc); s3 = f.x + f.y;
            }
            s0 += __shfl_xor_sync(0xffffffffu, s2, 16);
            s1 += __shfl_xor_sync(0xffffffffu, s3, 16);
            s0 += __shfl_xor_sync(0xffffffffu, s1, 8);
            s0 += __shfl_xor_sync(0xffffffffu, s0, 4);
            s0 += __shfl_xor_sync(0xffffffffu, s0, 2);
            s0 += __shfl_xor_sync(0xffffffffu, s0, 1);
            pd[j] = s0;                     // full dot of row r0+q
        }
        // softmax over j for row r0+q (once per 4 rows; per-quarter data)
        float m01 = fmaxf(pd[0], pd[1]), m23 = fmaxf(pd[2], pd[3]);
        float m45 = fmaxf(pd[4], pd[5]), m67 = fmaxf(pd[6], pd[7]);
        float m89 = fmaxf(pd[8], pd[9]);
        float mx = fmaxf(fmaxf(fmaxf(m01, m23), fmaxf(m45, m67)), m89);
        float Z = 0.f;
#pragma unroll
        for (int j = 0; j < J_; j++) { pd[j] = __expf(pd[j] - mx); Z += pd[j]; }
        float rZ = __fdividef(1.0f, Z);
        // accumulate: coefficient for slot r = shfl_xor(c_own, 8r)
#pragma unroll
        for (int j = 0; j < J_; j++) {
            float c0 = pd[j] * rZ;                        // row q
            float c1 = __shfl_xor_sync(0xffffffffu, c0, 8);   // row q^1
            float c2 = __shfl_xor_sync(0xffffffffu, c0, 16);  // row q^2
            float c3 = __shfl_xor_sync(0xffffffffu, c0, 24);  // row q^3
            u64 cc;
            cc = pack2(c0, c0);
            p20[j] = ffma2(cc, a0[0], p20[j]);
            p21[j] = ffma2(cc, a1[0], p21[j]);
            cc = pack2(c1, c1);
            p20[j] = ffma2(cc, a0[1], p20[j]);
            p21[j] = ffma2(cc, a1[1], p21[j]);
            cc = pack2(c2, c2);
            p20[j] = ffma2(cc, a0[2], p20[j]);
            p21[j] = ffma2(cc, a1[2], p21[j]);
            cc = pack2(c3, c3);
            p20[j] = ffma2(cc, a0[3], p20[j]);
            p21[j] = ffma2(cc, a1[3], p21[j]);
        }
    }

    // aggregate the 8 warps via smem, then 1 coalesced gmem atomic pass
#pragma unroll
    for (int j = 0; j < J_; j++) {
        float2 a = unpack2(p20[j]);
        float2 c = unpack2(p21[j]);
        float* d = ps + j*K_ + lane*4;
        atomicAdd(d+0, a.x); atomicAdd(d+1, a.y);
        atomicAdd(d+2, c.x); atomicAdd(d+3, c.y);
    }
    __syncthreads();
    float* pb = p + b*J_*K_;
    for (int i = tid; i < J_*K_; i += 256)
        atomicAdd(pb + i, ps[i]);
}

// o2[b,j,d] = sum_k p2[b,j,k]*W[k,jd]; out = squash(o2) over d
__global__ void k_final(const float* __restrict__ W, float* __restrict__ out) {
    int b = blockIdx.x, t = threadIdx.x;   // 160 threads
    int j = t >> 4;
    __shared__ float so[F_];
    const float* pj = g_p2 + b*J_*K_ + j*K_;
    const float* wcol = W + t;
    float acc = 0.f;
#pragma unroll 8
    for (int k = 0; k < K_; k++) acc += pj[k] * wcol[k*F_];
    so[t] = acc;
    __syncthreads();
    float s2 = 0.f;
#pragma unroll
    for (int d2 = 0; d2 < D_; d2++) { float x = so[j*D_ + d2]; s2 += x*x; }
    out[b*F_ + t] = acc * s2 / ((1.f + s2) * sqrtf(s2 + 1e-7f));
}

extern "C" void kernel_launch(void* const* d_in, const int* in_sizes, int n_in,
                              void* d_out, int out_size) {
    const float* u = (const float*)d_in[0];
    const float* W = (const float*)d_in[1];
    float* out = (float*)d_out;

    k_init<<<(B_*J_*K_ + 255)/256, 256>>>();
    k_sum<<<dim3(8, B_), 256>>>(u);
    k_ov<<<B_, F_>>>(W, 0);          // o0 (c uniform), v1
    k_pass<<<512, 256>>>(u, 0);      // b1 -> softmax -> p1
    k_ov<<<B_, F_>>>(W, 1);          // o1, v2
    k_pass<<<512, 256>>>(u, 1);      // b2 -> softmax -> p2
    k_final<<<B_, F_>>>(W, out);     // o2 -> squash
}